// round 15
// baseline (speedup 1.0000x reference)
#include <cuda_runtime.h>
#include <cuda_fp16.h>

#define BB 2
#define CC 256
#define HH 200
#define WW 200
#define KK 1000
#define NSAMP 14   // POOLED * S = 7*2 per axis
#define NBINS 49
#define CHALF 128  // channels per block (half of C)

// NHWC fp16 scratch: [B][H][W][C]. Viewed as uint4 = 8 halves (8 channels).
// 2*200*200*256 * 2B = 40.96 MB -> fully L2-resident during gather.
__device__ uint4 g_xt[(size_t)BB * HH * WW * (CC / 8)];

// ---------------------------------------------------------------------------
// Transpose+convert x[B,C,H,W] f32 -> g_xt[B,H,W,C] f16 (v1 — measured best).
// Per (b,h) slice, tile = 64 C x 32 W, block (32,8).
// ---------------------------------------------------------------------------
__global__ void transpose_f16_kernel(const float* __restrict__ x) {
    __shared__ float tile[64][33];
    int bh = blockIdx.z;
    int b = bh / HH, h = bh % HH;
    int w0 = blockIdx.x * 32, c0 = blockIdx.y * 64;
    int tx = threadIdx.x, ty = threadIdx.y;

#pragma unroll
    for (int i = 0; i < 64; i += 8) {
        int c = c0 + ty + i, w = w0 + tx;
        if (w < WW)
            tile[ty + i][tx] = x[(((size_t)b * CC + c) * HH + h) * WW + w];
    }
    __syncthreads();

    __half2* xt = (__half2*)g_xt;
#pragma unroll
    for (int i = 0; i < 32; i += 8) {
        int w = w0 + ty + i;
        if (w < WW) {
            float lo = tile[2 * tx][ty + i];
            float hi = tile[2 * tx + 1][ty + i];
            size_t hidx = ((((size_t)b * HH + h) * WW + w) * CC + c0 + 2 * tx) >> 1;
            xt[hidx] = __floats2half2_rn(lo, hi);
        }
    }
}

// ---------------------------------------------------------------------------
// RoIAlign gather: one block per (ROI, channel-half). grid = (1000, 2),
// 256 threads.
//   qloc = (t & 15) -> 8-channel octet within the half (uint4 = 8 fp16 ch)
//   g    = (t >> 4) -> bin group (16 groups stride over 49 bins)
// 196 sample-point weight quads precomputed into s_wtab (1 LDS.128/point).
// Per point: 4 corner uint4 loads, fp16 HMUL2/HFMA2 4-corner combine, one
// f16x2->f32 convert, fp32 accumulation (1/4 averaging folded into weights).
// Output half-tile [128][49] f32 staged in SMEM, coalesced float4 flush.
// __launch_bounds__(256, 6): 42-reg cap -> 6 blocks/SM (was 5; occ 55% with
// L1-latency-bound loop -> raise resident warps).
// ---------------------------------------------------------------------------
__global__ __launch_bounds__(256, 6) void roialign_kernel(
    const float* __restrict__ rois, float* __restrict__ out) {
    int k = blockIdx.x;
    int half = blockIdx.y;
    __shared__ int   s_lo[2 * NSAMP], s_hi[2 * NSAMP];
    __shared__ float s_w0[2 * NSAMP], s_w1[2 * NSAMP];
    __shared__ int   s_b;
    __shared__ uint4 s_wtab[NSAMP * NSAMP];       // 196 * 16B = 3136 B
    __shared__ float4 out_s4[CHALF * NBINS / 4];  // 25088 B, 16B-aligned
    float* out_s = (float*)out_s4;

    int t = threadIdx.x;
    if (t == 0) s_b = (int)rois[k * 5];
    if (t < 2 * NSAMP) {
        // t in [0, NSAMP): y axis; t in [NSAMP, 2*NSAMP): x axis
        int isx = (t >= NSAMP) ? 1 : 0;
        int idx = isx ? t - NSAMP : t;
        float r1 = rois[k * 5 + (isx ? 1 : 2)];
        float r2 = rois[k * 5 + (isx ? 3 : 4)];
        int limit = isx ? WW : HH;
        float start = r1 * 0.25f - 0.5f;          // SPATIAL_SCALE, aligned offset
        float endv  = r2 * 0.25f - 0.5f;
        float binsz = (endv - start) * (1.0f / 7.0f);
        int p  = idx >> 1;                        // pooled bin
        int si = idx & 1;                         // sample within bin
        float coord = start + ((float)p + ((float)si + 0.5f) * 0.5f) * binsz;
        // validity folded into weight; 0.5 per axis => 1/4 grid average total
        float validf = (coord >= -1.0f && coord <= (float)limit) ? 0.5f : 0.0f;
        float cc = fmaxf(coord, 0.0f);
        int low0 = (int)floorf(cc);
        int cap  = (low0 >= limit - 1) ? 1 : 0;
        int low  = cap ? limit - 1 : low0;
        int high = cap ? limit - 1 : low0 + 1;
        if (cap) cc = (float)low;
        float l = cc - (float)low;
        float h = 1.0f - l;
        s_lo[t] = low;
        s_hi[t] = high;
        s_w0[t] = h * validf;
        s_w1[t] = l * validf;
    }
    __syncthreads();

    // Precompute all 196 point-weight quads (broadcast half2 each).
    if (t < NSAMP * NSAMP) {
        int ys = t / NSAMP, xs = t - (t / NSAMP) * NSAMP;
        float wy0 = s_w0[ys], wy1 = s_w1[ys];
        float wx0 = s_w0[NSAMP + xs], wx1 = s_w1[NSAMP + xs];
        __half2 h00 = __float2half2_rn(wy0 * wx0);
        __half2 h01 = __float2half2_rn(wy0 * wx1);
        __half2 h10 = __float2half2_rn(wy1 * wx0);
        __half2 h11 = __float2half2_rn(wy1 * wx1);
        uint4 v;
        v.x = *(unsigned int*)&h00;
        v.y = *(unsigned int*)&h01;
        v.z = *(unsigned int*)&h10;
        v.w = *(unsigned int*)&h11;
        s_wtab[t] = v;
    }
    __syncthreads();

    int b = s_b;
    const uint4* __restrict__ basev = g_xt + (size_t)b * (HH * WW) * (CC / 8);
    int qloc = t & 15;
    int g = t >> 4;
    int q = half * (CHALF / 8) + qloc;  // global 8-channel octet

    for (int bin = g; bin < NBINS; bin += 16) {
        int ph = bin / 7;
        int pw = bin - ph * 7;
        float acc0 = 0.f, acc1 = 0.f, acc2 = 0.f, acc3 = 0.f;
        float acc4 = 0.f, acc5 = 0.f, acc6 = 0.f, acc7 = 0.f;
#pragma unroll
        for (int j = 0; j < 2; j++) {
            int ys = 2 * ph + j;
            int ry0 = s_lo[ys] * WW;
            int ry1 = s_hi[ys] * WW;
#pragma unroll
            for (int i = 0; i < 2; i++) {
                int xs = 2 * pw + i;
                int x0 = s_lo[NSAMP + xs], x1 = s_hi[NSAMP + xs];
                uint4 wv = s_wtab[ys * NSAMP + xs];
                __half2 h00 = *(__half2*)&wv.x;
                __half2 h01 = *(__half2*)&wv.y;
                __half2 h10 = *(__half2*)&wv.z;
                __half2 h11 = *(__half2*)&wv.w;
                uint4 u00 = basev[(ry0 + x0) * (CC / 8) + q];
                uint4 u01 = basev[(ry0 + x1) * (CC / 8) + q];
                uint4 u10 = basev[(ry1 + x0) * (CC / 8) + q];
                uint4 u11 = basev[(ry1 + x1) * (CC / 8) + q];
                const __half2* p00 = (const __half2*)&u00;
                const __half2* p01 = (const __half2*)&u01;
                const __half2* p10 = (const __half2*)&u10;
                const __half2* p11 = (const __half2*)&u11;
                // 4-corner convex combine in fp16, one convert, f32 accumulate
                __half2 hv0 = __hmul2(p00[0], h00);
                __half2 hv1 = __hmul2(p00[1], h00);
                __half2 hv2 = __hmul2(p00[2], h00);
                __half2 hv3 = __hmul2(p00[3], h00);
                hv0 = __hfma2(p01[0], h01, hv0);
                hv1 = __hfma2(p01[1], h01, hv1);
                hv2 = __hfma2(p01[2], h01, hv2);
                hv3 = __hfma2(p01[3], h01, hv3);
                hv0 = __hfma2(p10[0], h10, hv0);
                hv1 = __hfma2(p10[1], h10, hv1);
                hv2 = __hfma2(p10[2], h10, hv2);
                hv3 = __hfma2(p10[3], h10, hv3);
                hv0 = __hfma2(p11[0], h11, hv0);
                hv1 = __hfma2(p11[1], h11, hv1);
                hv2 = __hfma2(p11[2], h11, hv2);
                hv3 = __hfma2(p11[3], h11, hv3);
                float2 f0 = __half22float2(hv0);
                float2 f1 = __half22float2(hv1);
                float2 f2 = __half22float2(hv2);
                float2 f3 = __half22float2(hv3);
                acc0 += f0.x; acc1 += f0.y;
                acc2 += f1.x; acc3 += f1.y;
                acc4 += f2.x; acc5 += f2.y;
                acc6 += f3.x; acc7 += f3.y;
            }
        }
        int cb = qloc * 8;  // channel within half
        out_s[(cb + 0) * NBINS + bin] = acc0;
        out_s[(cb + 1) * NBINS + bin] = acc1;
        out_s[(cb + 2) * NBINS + bin] = acc2;
        out_s[(cb + 3) * NBINS + bin] = acc3;
        out_s[(cb + 4) * NBINS + bin] = acc4;
        out_s[(cb + 5) * NBINS + bin] = acc5;
        out_s[(cb + 6) * NBINS + bin] = acc6;
        out_s[(cb + 7) * NBINS + bin] = acc7;
    }
    __syncthreads();

    // Coalesced flush: this half's out region is contiguous (128*49 f32,
    // 25088 B; offsets are multiples of 16B).
    float4* outk = (float4*)(out + ((size_t)k * CC + half * CHALF) * NBINS);
    for (int i = t; i < CHALF * NBINS / 4; i += 256) outk[i] = out_s4[i];
}

extern "C" void kernel_launch(void* const* d_in, const int* in_sizes, int n_in,
                              void* d_out, int out_size) {
    const float* x    = (const float*)d_in[0];
    const float* rois = (const float*)d_in[1];
    float* out = (float*)d_out;

    // 1) NHWC fp16 transpose of the feature map into device scratch
    dim3 tb(32, 8);
    dim3 tg((WW + 31) / 32, CC / 64, BB * HH);  // (7, 4, 400)
    transpose_f16_kernel<<<tg, tb>>>(x);

    // 2) RoIAlign gather: one block per (ROI, channel-half)
    roialign_kernel<<<dim3(KK, 2), 256>>>(rois, out);
}

// round 16
// speedup vs baseline: 1.1725x; 1.1725x over previous
#include <cuda_runtime.h>
#include <cuda_fp16.h>

#define BB 2
#define CC 256
#define HH 200
#define WW 200
#define KK 1000
#define NSAMP 14   // POOLED * S = 7*2 per axis
#define NBINS 49
#define CHALF 128  // channels per block (half of C)

// NHWC fp16 scratch: [B][H][W][C]. Viewed as uint4 = 8 halves (8 channels).
// 2*200*200*256 * 2B = 40.96 MB -> fully L2-resident during gather.
__device__ uint4 g_xt[(size_t)BB * HH * WW * (CC / 8)];

// ---------------------------------------------------------------------------
// Transpose+convert x[B,C,H,W] f32 -> g_xt[B,H,W,C] f16 (v1 — measured best).
// Per (b,h) slice, tile = 64 C x 32 W, block (32,8).
// ---------------------------------------------------------------------------
__global__ void transpose_f16_kernel(const float* __restrict__ x) {
    __shared__ float tile[64][33];
    int bh = blockIdx.z;
    int b = bh / HH, h = bh % HH;
    int w0 = blockIdx.x * 32, c0 = blockIdx.y * 64;
    int tx = threadIdx.x, ty = threadIdx.y;

#pragma unroll
    for (int i = 0; i < 64; i += 8) {
        int c = c0 + ty + i, w = w0 + tx;
        if (w < WW)
            tile[ty + i][tx] = x[(((size_t)b * CC + c) * HH + h) * WW + w];
    }
    __syncthreads();

    __half2* xt = (__half2*)g_xt;
#pragma unroll
    for (int i = 0; i < 32; i += 8) {
        int w = w0 + ty + i;
        if (w < WW) {
            float lo = tile[2 * tx][ty + i];
            float hi = tile[2 * tx + 1][ty + i];
            size_t hidx = ((((size_t)b * HH + h) * WW + w) * CC + c0 + 2 * tx) >> 1;
            xt[hidx] = __floats2half2_rn(lo, hi);
        }
    }
}

// ---------------------------------------------------------------------------
// RoIAlign gather: one block per (ROI, channel-half). grid = (1000, 2),
// 256 threads.
//   qloc = (t & 15) -> 8-channel octet within the half (uint4 = 8 fp16 ch)
//   g    = (t >> 4) -> bin group (16 groups stride over 49 bins)
// 196 sample-point weight quads precomputed into s_wtab (1 LDS.128/point).
// Per point: 4 corner uint4 loads, fp16 HMUL2/HFMA2 4-corner combine, one
// f16x2->f32 convert, fp32 accumulation (1/4 averaging folded into weights).
// Output half-tile [128][49] f32 staged in SMEM, coalesced float4 flush.
// __launch_bounds__(256, 4): 64-reg budget. Measured reg/MLP curve:
// 40regs/6blk -> 45.9us, 48regs/5blk -> 38.0us; kernel is per-warp-MLP-bound
// (16 independent LDG.128 per bin need dest regs in flight), so give ptxas
// headroom to front-batch more loads at a modest occupancy cost.
// ---------------------------------------------------------------------------
__global__ __launch_bounds__(256, 4) void roialign_kernel(
    const float* __restrict__ rois, float* __restrict__ out) {
    int k = blockIdx.x;
    int half = blockIdx.y;
    __shared__ int   s_lo[2 * NSAMP], s_hi[2 * NSAMP];
    __shared__ float s_w0[2 * NSAMP], s_w1[2 * NSAMP];
    __shared__ int   s_b;
    __shared__ uint4 s_wtab[NSAMP * NSAMP];       // 196 * 16B = 3136 B
    __shared__ float4 out_s4[CHALF * NBINS / 4];  // 25088 B, 16B-aligned
    float* out_s = (float*)out_s4;

    int t = threadIdx.x;
    if (t == 0) s_b = (int)rois[k * 5];
    if (t < 2 * NSAMP) {
        // t in [0, NSAMP): y axis; t in [NSAMP, 2*NSAMP): x axis
        int isx = (t >= NSAMP) ? 1 : 0;
        int idx = isx ? t - NSAMP : t;
        float r1 = rois[k * 5 + (isx ? 1 : 2)];
        float r2 = rois[k * 5 + (isx ? 3 : 4)];
        int limit = isx ? WW : HH;
        float start = r1 * 0.25f - 0.5f;          // SPATIAL_SCALE, aligned offset
        float endv  = r2 * 0.25f - 0.5f;
        float binsz = (endv - start) * (1.0f / 7.0f);
        int p  = idx >> 1;                        // pooled bin
        int si = idx & 1;                         // sample within bin
        float coord = start + ((float)p + ((float)si + 0.5f) * 0.5f) * binsz;
        // validity folded into weight; 0.5 per axis => 1/4 grid average total
        float validf = (coord >= -1.0f && coord <= (float)limit) ? 0.5f : 0.0f;
        float cc = fmaxf(coord, 0.0f);
        int low0 = (int)floorf(cc);
        int cap  = (low0 >= limit - 1) ? 1 : 0;
        int low  = cap ? limit - 1 : low0;
        int high = cap ? limit - 1 : low0 + 1;
        if (cap) cc = (float)low;
        float l = cc - (float)low;
        float h = 1.0f - l;
        s_lo[t] = low;
        s_hi[t] = high;
        s_w0[t] = h * validf;
        s_w1[t] = l * validf;
    }
    __syncthreads();

    // Precompute all 196 point-weight quads (broadcast half2 each).
    if (t < NSAMP * NSAMP) {
        int ys = t / NSAMP, xs = t - (t / NSAMP) * NSAMP;
        float wy0 = s_w0[ys], wy1 = s_w1[ys];
        float wx0 = s_w0[NSAMP + xs], wx1 = s_w1[NSAMP + xs];
        __half2 h00 = __float2half2_rn(wy0 * wx0);
        __half2 h01 = __float2half2_rn(wy0 * wx1);
        __half2 h10 = __float2half2_rn(wy1 * wx0);
        __half2 h11 = __float2half2_rn(wy1 * wx1);
        uint4 v;
        v.x = *(unsigned int*)&h00;
        v.y = *(unsigned int*)&h01;
        v.z = *(unsigned int*)&h10;
        v.w = *(unsigned int*)&h11;
        s_wtab[t] = v;
    }
    __syncthreads();

    int b = s_b;
    const uint4* __restrict__ basev = g_xt + (size_t)b * (HH * WW) * (CC / 8);
    int qloc = t & 15;
    int g = t >> 4;
    int q = half * (CHALF / 8) + qloc;  // global 8-channel octet

    for (int bin = g; bin < NBINS; bin += 16) {
        int ph = bin / 7;
        int pw = bin - ph * 7;
        float acc0 = 0.f, acc1 = 0.f, acc2 = 0.f, acc3 = 0.f;
        float acc4 = 0.f, acc5 = 0.f, acc6 = 0.f, acc7 = 0.f;
#pragma unroll
        for (int j = 0; j < 2; j++) {
            int ys = 2 * ph + j;
            int ry0 = s_lo[ys] * WW;
            int ry1 = s_hi[ys] * WW;
#pragma unroll
            for (int i = 0; i < 2; i++) {
                int xs = 2 * pw + i;
                int x0 = s_lo[NSAMP + xs], x1 = s_hi[NSAMP + xs];
                uint4 wv = s_wtab[ys * NSAMP + xs];
                __half2 h00 = *(__half2*)&wv.x;
                __half2 h01 = *(__half2*)&wv.y;
                __half2 h10 = *(__half2*)&wv.z;
                __half2 h11 = *(__half2*)&wv.w;
                uint4 u00 = basev[(ry0 + x0) * (CC / 8) + q];
                uint4 u01 = basev[(ry0 + x1) * (CC / 8) + q];
                uint4 u10 = basev[(ry1 + x0) * (CC / 8) + q];
                uint4 u11 = basev[(ry1 + x1) * (CC / 8) + q];
                const __half2* p00 = (const __half2*)&u00;
                const __half2* p01 = (const __half2*)&u01;
                const __half2* p10 = (const __half2*)&u10;
                const __half2* p11 = (const __half2*)&u11;
                // 4-corner convex combine in fp16, one convert, f32 accumulate
                __half2 hv0 = __hmul2(p00[0], h00);
                __half2 hv1 = __hmul2(p00[1], h00);
                __half2 hv2 = __hmul2(p00[2], h00);
                __half2 hv3 = __hmul2(p00[3], h00);
                hv0 = __hfma2(p01[0], h01, hv0);
                hv1 = __hfma2(p01[1], h01, hv1);
                hv2 = __hfma2(p01[2], h01, hv2);
                hv3 = __hfma2(p01[3], h01, hv3);
                hv0 = __hfma2(p10[0], h10, hv0);
                hv1 = __hfma2(p10[1], h10, hv1);
                hv2 = __hfma2(p10[2], h10, hv2);
                hv3 = __hfma2(p10[3], h10, hv3);
                hv0 = __hfma2(p11[0], h11, hv0);
                hv1 = __hfma2(p11[1], h11, hv1);
                hv2 = __hfma2(p11[2], h11, hv2);
                hv3 = __hfma2(p11[3], h11, hv3);
                float2 f0 = __half22float2(hv0);
                float2 f1 = __half22float2(hv1);
                float2 f2 = __half22float2(hv2);
                float2 f3 = __half22float2(hv3);
                acc0 += f0.x; acc1 += f0.y;
                acc2 += f1.x; acc3 += f1.y;
                acc4 += f2.x; acc5 += f2.y;
                acc6 += f3.x; acc7 += f3.y;
            }
        }
        int cb = qloc * 8;  // channel within half
        out_s[(cb + 0) * NBINS + bin] = acc0;
        out_s[(cb + 1) * NBINS + bin] = acc1;
        out_s[(cb + 2) * NBINS + bin] = acc2;
        out_s[(cb + 3) * NBINS + bin] = acc3;
        out_s[(cb + 4) * NBINS + bin] = acc4;
        out_s[(cb + 5) * NBINS + bin] = acc5;
        out_s[(cb + 6) * NBINS + bin] = acc6;
        out_s[(cb + 7) * NBINS + bin] = acc7;
    }
    __syncthreads();

    // Coalesced flush: this half's out region is contiguous (128*49 f32,
    // 25088 B; offsets are multiples of 16B).
    float4* outk = (float4*)(out + ((size_t)k * CC + half * CHALF) * NBINS);
    for (int i = t; i < CHALF * NBINS / 4; i += 256) outk[i] = out_s4[i];
}

extern "C" void kernel_launch(void* const* d_in, const int* in_sizes, int n_in,
                              void* d_out, int out_size) {
    const float* x    = (const float*)d_in[0];
    const float* rois = (const float*)d_in[1];
    float* out = (float*)d_out;

    // 1) NHWC fp16 transpose of the feature map into device scratch
    dim3 tb(32, 8);
    dim3 tg((WW + 31) / 32, CC / 64, BB * HH);  // (7, 4, 400)
    transpose_f16_kernel<<<tg, tb>>>(x);

    // 2) RoIAlign gather: one block per (ROI, channel-half)
    roialign_kernel<<<dim3(KK, 2), 256>>>(rois, out);
}